// round 6
// baseline (speedup 1.0000x reference)
#include <cuda_runtime.h>
#include <cstdint>

// ---------------------------------------------------------------------------
// RipsECC. B=4096 points in [0,1]^3, 64 bins, bin(d) = ceil(31.5*d) in [0,55].
// All C(4096,2)=8,386,560 pairs are edges. out = cumsum(+4096 at bin0 - hist).
//
// 148 blocks x 1024 threads. 32 super-blocks (SB) of 128 rows; lane owns the
// 4 points i_q = 128s + 32q + lane (q=0..3) in registers. Per j: ONE broadcast
// LDS.128 serves 4 pairs (4 independent bin chains). Units = 16-j chunks:
// per SB s, 8 diagonal chunks (predicate j>i) + 8*(31-s) off-diagonal chunks;
// prefix(s) = 4s(65-s); 4224 units over 4736 warp-slots.
// u16 histograms: warp-pair shares a u32 word (halfword stores, race-free);
// 16 regions x 64 bins x 32 lanes = 128 KB.
// ---------------------------------------------------------------------------

#define NPTS      4096
#define NSTEPS    64
#define NTHREADS  1024
#define NBLOCKS   148
#define NUNITS    4224
#define NREGIONS  16
#define HIST_WORDS (NREGIONS * NSTEPS * 32)        // 32768 words = 128 KB
#define SMEM_BYTES (NPTS * 16 + HIST_WORDS * 4)    // 64KB + 128KB

__device__ int      g_part[NBLOCKS][NSTEPS];
__device__ unsigned g_ticket = 0;

// bin = ceil(31.5*d) = ceil(sqrt(m)); m = 992.25*d2 via norm expansion.
__device__ __forceinline__ int bin_of(float A, float B, float C, float Kw,
                                      float4 p) {
    float m = fmaf(A, p.x, fmaf(B, p.y, fmaf(C, p.z, Kw)));
    float d;
    asm("sqrt.approx.f32 %0, %1;" : "=f"(d) : "f"(m));   // MUFU.SQRT
    return __float2int_ru(d);                            // t in [0, 55]
}

extern __shared__ float4 smem4[];

__global__ void __launch_bounds__(NTHREADS, 1)
rips_ecc_kernel(const float* __restrict__ x, float* __restrict__ out) {
    float4*   pts  = smem4;                       // [4096] (x,y,z, 992.25|p|^2)
    unsigned* hist = (unsigned*)(smem4 + NPTS);   // [16][64][32] u32 words

    const int tid = threadIdx.x;

    // Coalesced staging: thread t loads points 4t..4t+3 via 3x LDG.128.
    {
        const float4* xv = (const float4*)x;      // 12288 floats = 3072 float4
        float4 v0 = xv[3 * tid + 0];
        float4 v1 = xv[3 * tid + 1];
        float4 v2 = xv[3 * tid + 2];
        // points: (v0.x,v0.y,v0.z) (v0.w,v1.x,v1.y) (v1.z,v1.w,v2.x) (v2.y,v2.z,v2.w)
        pts[4 * tid + 0] = make_float4(v0.x, v0.y, v0.z,
            992.25f * fmaf(v0.x, v0.x, fmaf(v0.y, v0.y, v0.z * v0.z)));
        pts[4 * tid + 1] = make_float4(v0.w, v1.x, v1.y,
            992.25f * fmaf(v0.w, v0.w, fmaf(v1.x, v1.x, v1.y * v1.y)));
        pts[4 * tid + 2] = make_float4(v1.z, v1.w, v2.x,
            992.25f * fmaf(v1.z, v1.z, fmaf(v1.w, v1.w, v2.x * v2.x)));
        pts[4 * tid + 3] = make_float4(v2.y, v2.z, v2.w,
            992.25f * fmaf(v2.y, v2.y, fmaf(v2.z, v2.z, v2.w * v2.w)));
    }
    uint4* h4 = (uint4*)hist;
    for (int i = tid; i < HIST_WORDS / 4; i += NTHREADS)
        h4[i] = make_uint4(0u, 0u, 0u, 0u);
    __syncthreads();

    const int warp = tid >> 5;
    const int lane = tid & 31;
    // u16 bank: region = warp>>1 (8192 B), halfword slot = lane*2 + (warp&1).
    unsigned short* myh = (unsigned short*)((char*)hist + (warp >> 1) * 8192)
                          + lane * 2 + (warp & 1);

    const int u = warp * NBLOCKS + blockIdx.x;
    if (u < NUNITS) {
        // prefix(s) = 4s(65-s); s = floor((65 - sqrt(4225-u))/2), fixup +-1.
        int s = (int)(0.5f * (65.0f - sqrtf((float)(4225 - u))));
        s = max(0, min(31, s));
        while (s > 0  && 4 * s * (65 - s) > u) --s;
        while (s < 31 && 4 * (s + 1) * (64 - s) <= u) ++s;
        const int rem   = u - 4 * s * (65 - s);   // [0, 8*(32-s))
        const int sbase = s << 7;

        float4 q0 = pts[sbase + lane];
        float4 q1 = pts[sbase + 32 + lane];
        float4 q2 = pts[sbase + 64 + lane];
        float4 q3 = pts[sbase + 96 + lane];
        const float A0 = -1984.5f * q0.x, B0 = -1984.5f * q0.y,
                    C0 = -1984.5f * q0.z, K0 = q0.w;
        const float A1 = -1984.5f * q1.x, B1 = -1984.5f * q1.y,
                    C1 = -1984.5f * q1.z, K1 = q1.w;
        const float A2 = -1984.5f * q2.x, B2 = -1984.5f * q2.y,
                    C2 = -1984.5f * q2.z, K2 = q2.w;
        const float A3 = -1984.5f * q3.x, B3 = -1984.5f * q3.y,
                    C3 = -1984.5f * q3.z, K3 = q3.w;

        if (rem < 8) {
            // Diagonal chunk: j = sbase + 16*rem + jj; count pair (i_q, j)
            // only when j > i_q, i.e. jrel > 32q + lane.
            const int jr0 = rem << 4;
            #pragma unroll
            for (int jj = 0; jj < 16; jj++) {
                int jrel = jr0 + jj;
                float4 p = pts[sbase + jrel];
                int t0 = bin_of(A0, B0, C0, K0 + p.w, p);
                int t1 = bin_of(A1, B1, C1, K1 + p.w, p);
                int t2 = bin_of(A2, B2, C2, K2 + p.w, p);
                int t3 = bin_of(A3, B3, C3, K3 + p.w, p);
                if (jrel > lane)      myh[t0 << 6] += (unsigned short)1;
                if (jrel > lane + 32) myh[t1 << 6] += (unsigned short)1;
                if (jrel > lane + 64) myh[t2 << 6] += (unsigned short)1;
                if (jrel > lane + 96) myh[t3 << 6] += (unsigned short)1;
            }
        } else {
            // Off-diagonal chunk: 16 j's past the super-block.
            const int j0 = sbase + 128 + ((rem - 8) << 4);
            #pragma unroll
            for (int jj = 0; jj < 16; jj++) {
                float4 p = pts[j0 + jj];
                int t0 = bin_of(A0, B0, C0, K0 + p.w, p);
                int t1 = bin_of(A1, B1, C1, K1 + p.w, p);
                int t2 = bin_of(A2, B2, C2, K2 + p.w, p);
                int t3 = bin_of(A3, B3, C3, K3 + p.w, p);
                myh[t0 << 6] += (unsigned short)1;
                myh[t1 << 6] += (unsigned short)1;
                myh[t2 << 6] += (unsigned short)1;
                myh[t3 << 6] += (unsigned short)1;
            }
        }
    }
    __syncthreads();

    // Block reduction: warp w reduces bins {2w, 2w+1} across 16 regions;
    // each u32 word holds two warp-halfword counters (lo+hi, sums < 64K).
    #pragma unroll
    for (int bb = 0; bb < 2; bb++) {
        int bin = warp * 2 + bb;
        unsigned sacc = 0;
        #pragma unroll
        for (int r = 0; r < NREGIONS; r++)
            sacc += hist[r * 2048 + (bin << 5) + lane];
        sacc = (sacc & 0xFFFFu) + (sacc >> 16);
        #pragma unroll
        for (int o = 16; o > 0; o >>= 1)
            sacc += __shfl_down_sync(0xffffffffu, sacc, o);
        if (lane == 0)
            g_part[blockIdx.x][bin] = (int)sacc;
    }
    __threadfence();
    __syncthreads();

    __shared__ int s_last;
    if (tid == 0)
        s_last = (atomicAdd(&g_ticket, 1u) == NBLOCKS - 1);
    __syncthreads();
    if (!s_last) return;
    __threadfence();

    // --- last block: reduce 148x64 partials, cumsum, write, reset ---
    __shared__ int red[NSTEPS * 16];
    {
        int bin = tid & 63;
        int grp = tid >> 6;               // 0..15
        int sacc = 0;
        for (int b2 = grp; b2 < NBLOCKS; b2 += 16)
            sacc += g_part[b2][bin];
        red[bin * 16 + grp] = sacc;
    }
    __syncthreads();
    __shared__ int ecc[NSTEPS];
    if (tid < NSTEPS) {
        int tot = 0;
        #pragma unroll
        for (int g = 0; g < 16; g++) tot += red[tid * 16 + g];
        ecc[tid] = (tid == 0 ? NPTS : 0) - tot;
    }
    __syncthreads();
    if (tid < 32) {
        int e0 = ecc[tid];
        int e1 = ecc[tid + 32];
        #pragma unroll
        for (int d = 1; d < 32; d <<= 1) {
            int t = __shfl_up_sync(0xffffffffu, e0, d);
            if (tid >= d) e0 += t;
        }
        int tot = __shfl_sync(0xffffffffu, e0, 31);
        #pragma unroll
        for (int d = 1; d < 32; d <<= 1) {
            int t = __shfl_up_sync(0xffffffffu, e1, d);
            if (tid >= d) e1 += t;
        }
        e1 += tot;
        out[tid]      = (float)e0;
        out[tid + 32] = (float)e1;
    }
    if (tid == 0) g_ticket = 0;   // self-reset for graph replay
}

extern "C" void kernel_launch(void* const* d_in, const int* in_sizes, int n_in,
                              void* d_out, int out_size) {
    (void)in_sizes; (void)n_in; (void)out_size;
    const float* x = (const float*)d_in[0];
    float* out = (float*)d_out;

    cudaFuncSetAttribute(rips_ecc_kernel,
                         cudaFuncAttributeMaxDynamicSharedMemorySize, SMEM_BYTES);

    rips_ecc_kernel<<<NBLOCKS, NTHREADS, SMEM_BYTES>>>(x, out);
}